// round 3
// baseline (speedup 1.0000x reference)
#include <cuda_runtime.h>
#include <math.h>

#define NB 32
#define NT 128
#define NF 128
#define NG 512

// Scratch (allocation-free): A^T layout [b][i][t] and CTX [b][i][f]
__device__ float g_At[NB * NT * NT];
__device__ float g_CTX[NB * NT * NF];

__device__ __forceinline__ float sigf(float x) { return 1.0f / (1.0f + __expf(-x)); }

// ---------------------------------------------------------------------------
// K1: S = X_b @ Wd[:F]  (128x128 per batch), column-wise softmax over t,
//     store transposed: g_At[b][j][t] = softmax_t(S[t][j]).
// grid (4 j-tiles, 32 batches), 256 threads, 4x4 micro-tile.
// ---------------------------------------------------------------------------
__global__ __launch_bounds__(256)
void k1_attn(const float* __restrict__ X, const float* __restrict__ Wd)
{
    __shared__ float Xs[NT][33];    // [t][k-tile] padded
    __shared__ float Wds[32][32];   // [k][j]
    __shared__ float Ss[NT][33];    // logits tile for softmax

    const int b   = blockIdx.y;
    const int j0  = blockIdx.x * 32;
    const int tid = threadIdx.x;
    const int tx  = tid & 7;    // j quad: 8*4 = 32
    const int ty  = tid >> 3;   // t quad: 32*4 = 128

    const float* Xb = X + b * NT * NF;

    float acc[4][4] = {};
    for (int k0 = 0; k0 < NF; k0 += 32) {
        // stage X tile: 128 t x 32 k, float4 (8 vec per row, 1024 vecs, 256 thr)
        for (int idx = tid; idx < NT * 8; idx += 256) {
            int t = idx >> 3, kv = idx & 7;
            float4 v = *(const float4*)&Xb[t * NF + k0 + kv * 4];
            Xs[t][kv * 4 + 0] = v.x; Xs[t][kv * 4 + 1] = v.y;
            Xs[t][kv * 4 + 2] = v.z; Xs[t][kv * 4 + 3] = v.w;
        }
        // stage Wd tile: 32 k x 32 j
        for (int idx = tid; idx < 32 * 8; idx += 256) {
            int k = idx >> 3, jv = idx & 7;
            float4 v = *(const float4*)&Wd[(k0 + k) * NT + j0 + jv * 4];
            Wds[k][jv * 4 + 0] = v.x; Wds[k][jv * 4 + 1] = v.y;
            Wds[k][jv * 4 + 2] = v.z; Wds[k][jv * 4 + 3] = v.w;
        }
        __syncthreads();
#pragma unroll
        for (int k = 0; k < 32; ++k) {
            float xv[4], wv[4];
#pragma unroll
            for (int a = 0; a < 4; a++) xv[a] = Xs[ty * 4 + a][k];
#pragma unroll
            for (int c = 0; c < 4; c++) wv[c] = Wds[k][tx * 4 + c];
#pragma unroll
            for (int a = 0; a < 4; a++)
#pragma unroll
                for (int c = 0; c < 4; c++)
                    acc[a][c] += xv[a] * wv[c];
        }
        __syncthreads();
    }
#pragma unroll
    for (int a = 0; a < 4; a++)
#pragma unroll
        for (int c = 0; c < 4; c++)
            Ss[ty * 4 + a][tx * 4 + c] = acc[a][c];
    __syncthreads();

    // softmax over t (128 rows) for each of this block's 32 columns.
    // warp w handles columns w*4 .. w*4+3; each lane owns 4 t's.
    const int w = tid >> 5, lane = tid & 31;
#pragma unroll
    for (int c = 0; c < 4; ++c) {
        const int jl = w * 4 + c;
        float v[4];
#pragma unroll
        for (int r = 0; r < 4; r++) v[r] = Ss[lane + 32 * r][jl];
        float m = fmaxf(fmaxf(v[0], v[1]), fmaxf(v[2], v[3]));
#pragma unroll
        for (int o = 16; o > 0; o >>= 1) m = fmaxf(m, __shfl_xor_sync(0xffffffffu, m, o));
        float s = 0.0f;
#pragma unroll
        for (int r = 0; r < 4; r++) { v[r] = __expf(v[r] - m); s += v[r]; }
#pragma unroll
        for (int o = 16; o > 0; o >>= 1) s += __shfl_xor_sync(0xffffffffu, s, o);
        const float inv = 1.0f / s;
        float* dst = g_At + (b * NT + (j0 + jl)) * NT;
#pragma unroll
        for (int r = 0; r < 4; r++) dst[lane + 32 * r] = v[r] * inv;
    }
}

// ---------------------------------------------------------------------------
// K2: CTX[b][i][f] = sum_t g_At[b][i][t] * X[b][t][f]
// grid (4 i-tiles, 32 batches), 256 threads, 4x4 micro-tile.
// ---------------------------------------------------------------------------
__global__ __launch_bounds__(256)
void k2_ctx(const float* __restrict__ X)
{
    __shared__ float Xs[32][NF];   // [t][f]
    __shared__ float As[32][33];   // [i][t] padded

    const int b   = blockIdx.y;
    const int i0  = blockIdx.x * 32;
    const int tid = threadIdx.x;
    const int tx  = tid & 31;   // f quad: 32*4 = 128
    const int ty  = tid >> 5;   // i quad: 8*4  = 32

    const float* Xb = X + b * NT * NF;
    const float* Ab = g_At + b * NT * NT;

    float acc[4][4] = {};
    for (int t0 = 0; t0 < NT; t0 += 32) {
        // stage X tile: 32 t x 128 f, float4
        for (int idx = tid; idx < 32 * 32; idx += 256) {
            int k = idx >> 5, fv = idx & 31;
            *(float4*)&Xs[k][fv * 4] = *(const float4*)&Xb[(t0 + k) * NF + fv * 4];
        }
        // stage A tile: 32 i x 32 t (padded rows -> scalar stores)
        for (int idx = tid; idx < 32 * 8; idx += 256) {
            int i = idx >> 3, tv = idx & 7;
            float4 v = *(const float4*)&Ab[(i0 + i) * NT + t0 + tv * 4];
            As[i][tv * 4 + 0] = v.x; As[i][tv * 4 + 1] = v.y;
            As[i][tv * 4 + 2] = v.z; As[i][tv * 4 + 3] = v.w;
        }
        __syncthreads();
#pragma unroll
        for (int k = 0; k < 32; ++k) {
            float av[4];
#pragma unroll
            for (int a = 0; a < 4; a++) av[a] = As[ty * 4 + a][k];
            float4 x4 = *(const float4*)&Xs[k][tx * 4];
            float xv[4] = {x4.x, x4.y, x4.z, x4.w};
#pragma unroll
            for (int a = 0; a < 4; a++)
#pragma unroll
                for (int c = 0; c < 4; c++)
                    acc[a][c] += av[a] * xv[c];
        }
        __syncthreads();
    }
    float* Cb = g_CTX + (b * NT + i0) * NF;
#pragma unroll
    for (int a = 0; a < 4; a++) {
        float4 v = make_float4(acc[a][0], acc[a][1], acc[a][2], acc[a][3]);
        *(float4*)&Cb[(ty * 4 + a) * NF + tx * 4] = v;
    }
}

// ---------------------------------------------------------------------------
// K3: z_g = CTX @ Wk[:, g] + bl  for g in {zi, zc, zo}  (skip unused zf),
//     h = sigmoid(zo) * tanh( sigmoid(zi) * tanh(zc) )
// grid (4 i-tiles, 32 batches), 256 threads.
// ---------------------------------------------------------------------------
__global__ __launch_bounds__(256)
void k3_out(const float* __restrict__ Wk, const float* __restrict__ bl,
            float* __restrict__ out)
{
    __shared__ float Cs[32][NF];   // [i][f]
    __shared__ float Wks[32][NF];  // [k][u], reused per gate/k-tile

    const int b   = blockIdx.y;
    const int i0  = blockIdx.x * 32;
    const int tid = threadIdx.x;
    const int tx  = tid & 31;   // u quad
    const int ty  = tid >> 5;   // i quad

    const float* Cb = g_CTX + (b * NT + i0) * NF;
    for (int idx = tid; idx < 32 * 32; idx += 256) {
        int i = idx >> 5, fv = idx & 31;
        *(float4*)&Cs[i][fv * 4] = *(const float4*)&Cb[i * NF + fv * 4];
    }

    const int gofs[3] = {0, 256, 384};   // zi, zc, zo column offsets
    float rg[3][4][4];

#pragma unroll
    for (int gi = 0; gi < 3; ++gi) {
        float acc[4][4] = {};
        for (int k0 = 0; k0 < NF; k0 += 32) {
            __syncthreads();   // protect Wks (and Cs on first pass)
            for (int idx = tid; idx < 32 * 32; idx += 256) {
                int k = idx >> 5, uv = idx & 31;
                *(float4*)&Wks[k][uv * 4] =
                    *(const float4*)&Wk[(k0 + k) * NG + gofs[gi] + uv * 4];
            }
            __syncthreads();
#pragma unroll
            for (int k = 0; k < 32; ++k) {
                float cv[4];
#pragma unroll
                for (int a = 0; a < 4; a++) cv[a] = Cs[ty * 4 + a][k0 + k];
                float4 w4 = *(const float4*)&Wks[k][tx * 4];
                float wv[4] = {w4.x, w4.y, w4.z, w4.w};
#pragma unroll
                for (int a = 0; a < 4; a++)
#pragma unroll
                    for (int c = 0; c < 4; c++)
                        acc[a][c] += cv[a] * wv[c];
            }
        }
#pragma unroll
        for (int a = 0; a < 4; a++)
#pragma unroll
            for (int c = 0; c < 4; c++)
                rg[gi][a][c] = acc[a][c] + __ldg(&bl[gofs[gi] + tx * 4 + c]);
    }

#pragma unroll
    for (int a = 0; a < 4; a++) {
        float h[4];
#pragma unroll
        for (int c = 0; c < 4; c++) {
            float cc = sigf(rg[0][a][c]) * tanhf(rg[1][a][c]);
            h[c] = sigf(rg[2][a][c]) * tanhf(cc);
        }
        float4 v = make_float4(h[0], h[1], h[2], h[3]);
        *(float4*)&out[(b * NT + i0 + ty * 4 + a) * NF + tx * 4] = v;
    }
}

extern "C" void kernel_launch(void* const* d_in, const int* in_sizes, int n_in,
                              void* d_out, int out_size)
{
    const float* X  = (const float*)d_in[0];   // (32,128,128)
    const float* Wd = (const float*)d_in[1];   // (256,128) -- only rows [0:128) matter
    const float* Wk = (const float*)d_in[3];   // (128,512)
    const float* bl = (const float*)d_in[5];   // (512,)
    float* out = (float*)d_out;                // (32,128,128)

    dim3 grid(4, NB);
    dim3 block(256);
    k1_attn<<<grid, block>>>(X, Wd);
    k2_ctx<<<grid, block>>>(X);
    k3_out<<<grid, block>>>(Wk, bl, out);
}

// round 4
// speedup vs baseline: 2.2930x; 2.2930x over previous
#include <cuda_runtime.h>
#include <math.h>

#define NB 32
#define NT 128
#define NF 128
#define NG 512

// SMEM strides (floats) — chosen for float4/LDS.128 alignment + conflict-free column reads
#define XS_S  132   // Xs [128][132]
#define WDS_S 36    // Wds[128][36]
#define SS_S  33    // Ss [128][33]
#define AS_S  132   // As [32][132]
#define CS_S  132   // Cs [32][132]
#define WKS_S 388   // Wks[32][388]  (3 gates x 128 + pad)

#define OFF_XS  0
#define OFF_WDS (OFF_XS  + NT * XS_S)    // 16896
#define OFF_SS  (OFF_WDS + NT * WDS_S)   // 21504
#define OFF_AS  (OFF_SS  + NT * SS_S)    // 25728
#define OFF_CS  (OFF_AS  + 32 * AS_S)    // 29952
#define OFF_WKS (OFF_CS  + 32 * CS_S)    // 34176
#define SMEM_FLOATS (OFF_WKS + 32 * WKS_S)  // 46592
#define SMEM_BYTES  (SMEM_FLOATS * 4)       // 186368

__device__ __forceinline__ float sigf(float x) { return 1.0f / (1.0f + __expf(-x)); }

// packed fp32x2 helpers
__device__ __forceinline__ void fma2(unsigned long long& d,
                                     unsigned long long a, unsigned long long b) {
    asm("fma.rn.f32x2 %0, %1, %2, %0;" : "+l"(d) : "l"(a), "l"(b));
}
__device__ __forceinline__ unsigned long long bcast2(float x) {
    unsigned long long d; unsigned int xi = __float_as_uint(x);
    asm("mov.b64 %0, {%1, %1};" : "=l"(d) : "r"(xi));
    return d;
}
__device__ __forceinline__ float2 unpk(unsigned long long v) {
    float2 f; asm("mov.b64 {%0, %1}, %2;" : "=f"(f.x), "=f"(f.y) : "l"(v));
    return f;
}

// ---------------------------------------------------------------------------
// Fully fused: per CTA = (batch b, 32 output rows i0..i0+31)
//   1) S[t][jl] = X_b @ Wd[:128, i0+jl]        (t=0..127, jl=0..31)
//   2) alpha[jl][t] = softmax_t S[t][jl]
//   3) CTX[jl][f] = sum_t alpha[jl][t] X_b[t][f]
//   4) z_g = CTX @ Wk[:, g] + bl (g in {zi,zc,zo}); h = sig(zo)*tanh(sig(zi)*tanh(zc))
// ---------------------------------------------------------------------------
__global__ __launch_bounds__(256, 1)
void fused_attn(const float* __restrict__ X, const float* __restrict__ Wd,
                const float* __restrict__ Wk, const float* __restrict__ bl,
                float* __restrict__ out)
{
    extern __shared__ float sm[];
    float* Xs  = sm + OFF_XS;
    float* Wds = sm + OFF_WDS;
    float* Ss  = sm + OFF_SS;
    float* As  = sm + OFF_AS;
    float* Cs  = sm + OFF_CS;
    float* Wks = sm + OFF_WKS;

    const int b   = blockIdx.y;
    const int i0  = blockIdx.x * 32;
    const int tid = threadIdx.x;

    const float* Xb = X + b * NT * NF;

    // ---- stage full X_b (128x128) and Wd[:128, i0:i0+32] ----
    for (int idx = tid; idx < NT * 32; idx += 256) {           // 4096 float4
        int t = idx >> 5, fv = idx & 31;
        *(float4*)&Xs[t * XS_S + fv * 4] = *(const float4*)&Xb[t * NF + fv * 4];
    }
    for (int idx = tid; idx < NT * 8; idx += 256) {            // 1024 float4
        int k = idx >> 3, jv = idx & 7;
        *(float4*)&Wds[k * WDS_S + jv * 4] = *(const float4*)&Wd[k * NT + i0 + jv * 4];
    }
    __syncthreads();

    // ---- K1: logits ----
    {
        const int tx = tid & 7;    // jl quad (8*4 = 32)
        const int ty = tid >> 3;   // t  quad (32*4 = 128)
        unsigned long long acc[4][2] = {};
#pragma unroll 4
        for (int k = 0; k < NF; ++k) {
            unsigned long long xx[4];
#pragma unroll
            for (int a = 0; a < 4; a++) xx[a] = bcast2(Xs[(ty * 4 + a) * XS_S + k]);
            ulonglong2 wp = *(const ulonglong2*)&Wds[k * WDS_S + tx * 4];
#pragma unroll
            for (int a = 0; a < 4; a++) { fma2(acc[a][0], xx[a], wp.x); fma2(acc[a][1], xx[a], wp.y); }
        }
#pragma unroll
        for (int a = 0; a < 4; a++) {
            float2 v0 = unpk(acc[a][0]), v1 = unpk(acc[a][1]);
            float* row = &Ss[(ty * 4 + a) * SS_S + tx * 4];
            row[0] = v0.x; row[1] = v0.y; row[2] = v1.x; row[3] = v1.y;
        }
    }
    __syncthreads();

    // ---- softmax over t per column (warp w -> columns w*4..w*4+3) ----
    {
        const int w = tid >> 5, lane = tid & 31;
#pragma unroll
        for (int c = 0; c < 4; ++c) {
            const int jl = w * 4 + c;
            float v[4];
#pragma unroll
            for (int r = 0; r < 4; r++) v[r] = Ss[(lane + 32 * r) * SS_S + jl];
            float m = fmaxf(fmaxf(v[0], v[1]), fmaxf(v[2], v[3]));
#pragma unroll
            for (int o = 16; o > 0; o >>= 1) m = fmaxf(m, __shfl_xor_sync(0xffffffffu, m, o));
            float s = 0.0f;
#pragma unroll
            for (int r = 0; r < 4; r++) { v[r] = __expf(v[r] - m); s += v[r]; }
#pragma unroll
            for (int o = 16; o > 0; o >>= 1) s += __shfl_xor_sync(0xffffffffu, s, o);
            const float inv = 1.0f / s;
#pragma unroll
            for (int r = 0; r < 4; r++) As[jl * AS_S + lane + 32 * r] = v[r] * inv;
        }
    }
    __syncthreads();

    // ---- K2: CTX rows ----
    {
        const int tx = tid & 31;   // f quad (32*4 = 128)
        const int ty = tid >> 5;   // i quad (8*4  = 32)
        unsigned long long acc[4][2] = {};
#pragma unroll 4
        for (int t = 0; t < NT; ++t) {
            unsigned long long aa[4];
#pragma unroll
            for (int a = 0; a < 4; a++) aa[a] = bcast2(As[(ty * 4 + a) * AS_S + t]);
            ulonglong2 xp = *(const ulonglong2*)&Xs[t * XS_S + tx * 4];
#pragma unroll
            for (int a = 0; a < 4; a++) { fma2(acc[a][0], aa[a], xp.x); fma2(acc[a][1], aa[a], xp.y); }
        }
#pragma unroll
        for (int a = 0; a < 4; a++) {
            ulonglong2 v; v.x = acc[a][0]; v.y = acc[a][1];
            *(ulonglong2*)&Cs[(ty * 4 + a) * CS_S + tx * 4] = v;
        }
    }
    __syncthreads();

    // ---- K3: 3 gates in one pass over k, Wk streamed in 32-row tiles ----
    {
        const int tx = tid & 31;   // u quad
        const int ty = tid >> 5;   // i quad
        const int gofs[3] = {0, 256, 384};   // zi, zc, zo
        unsigned long long acc[4][6] = {};

        for (int k0 = 0; k0 < NF; k0 += 32) {
            if (k0) __syncthreads();
            for (int idx = tid; idx < 32 * 96; idx += 256) {   // 3072 float4
                int k = idx / 96, v = idx % 96;
                int g = v >> 5, uv = v & 31;
                *(float4*)&Wks[k * WKS_S + g * 128 + uv * 4] =
                    *(const float4*)&Wk[(k0 + k) * NG + gofs[g] + uv * 4];
            }
            __syncthreads();
#pragma unroll 2
            for (int k = 0; k < 32; ++k) {
                unsigned long long cc[4];
#pragma unroll
                for (int a = 0; a < 4; a++) cc[a] = bcast2(Cs[(ty * 4 + a) * CS_S + k0 + k]);
#pragma unroll
                for (int g = 0; g < 3; ++g) {
                    ulonglong2 wp = *(const ulonglong2*)&Wks[k * WKS_S + g * 128 + tx * 4];
#pragma unroll
                    for (int a = 0; a < 4; a++) { fma2(acc[a][2 * g], cc[a], wp.x); fma2(acc[a][2 * g + 1], cc[a], wp.y); }
                }
            }
        }

        float blv[3][4];
#pragma unroll
        for (int g = 0; g < 3; ++g)
#pragma unroll
            for (int c = 0; c < 4; c++) blv[g][c] = __ldg(&bl[gofs[g] + tx * 4 + c]);

#pragma unroll
        for (int a = 0; a < 4; a++) {
            float z[3][4];
#pragma unroll
            for (int g = 0; g < 3; ++g) {
                float2 v0 = unpk(acc[a][2 * g]), v1 = unpk(acc[a][2 * g + 1]);
                z[g][0] = v0.x + blv[g][0]; z[g][1] = v0.y + blv[g][1];
                z[g][2] = v1.x + blv[g][2]; z[g][3] = v1.y + blv[g][3];
            }
            float h[4];
#pragma unroll
            for (int c = 0; c < 4; c++) {
                float cell = sigf(z[0][c]) * tanhf(z[1][c]);
                h[c] = sigf(z[2][c]) * tanhf(cell);
            }
            float4 v = make_float4(h[0], h[1], h[2], h[3]);
            *(float4*)&out[(b * NT + i0 + ty * 4 + a) * NF + tx * 4] = v;
        }
    }
}

extern "C" void kernel_launch(void* const* d_in, const int* in_sizes, int n_in,
                              void* d_out, int out_size)
{
    const float* X  = (const float*)d_in[0];   // (32,128,128)
    const float* Wd = (const float*)d_in[1];   // (256,128) -- only rows [0:128) matter
    const float* Wk = (const float*)d_in[3];   // (128,512)
    const float* bl = (const float*)d_in[5];   // (512,)
    float* out = (float*)d_out;                // (32,128,128)

    cudaFuncSetAttribute(fused_attn, cudaFuncAttributeMaxDynamicSharedMemorySize, SMEM_BYTES);
    fused_attn<<<dim3(4, NB), 256, SMEM_BYTES>>>(X, Wd, Wk, bl, out);
}